// round 9
// baseline (speedup 1.0000x reference)
#include <cuda_runtime.h>
#include <cuda_bf16.h>
#include <cuda_fp16.h>
#include <cstdint>

#define N_NODES 50000
#define N_EDGES 800000
#define IN_DIM  256
#define HID     128
#define LEAKY   0.01f

// ---------------- scratch (static device allocations only) ----------------
__device__ __align__(16) __half2 g_zh[N_NODES * (HID / 2)]; // fc output, fp16
__device__ __align__(16) float g_h1[N_NODES * HID];    // layer-1 result (ELU)
__device__ float g_s[N_NODES];                          // z . a[:D]
__device__ float g_t[N_NODES];                          // z . a[D:]
__device__ int   g_cnt[N_NODES];                        // in-degree histogram
__device__ int   g_rank[N_EDGES];                       // edge rank within dst seg
__device__ int   g_slot[N_EDGES];                       // CSR slot per edge
__device__ int   g_off[N_NODES + 1];                    // CSR offsets
__device__ int   g_csr[N_EDGES];                        // src id per CSR slot
__device__ float g_ex[N_EDGES];                         // exp(leaky(e)) per slot

__device__ __forceinline__ float elu1(float x) {
    return x > 0.f ? x : (__expf(x) - 1.f);
}

// ================= CSR build (once per call, reused by both layers) ========
__global__ void k_zero() {
    int i = blockIdx.x * blockDim.x + threadIdx.x;
    if (i < N_NODES) g_cnt[i] = 0;
}

// histogram; atomic return value = this edge's rank within its dst segment
__global__ void k_hist(const int* __restrict__ dst) {
    int i = blockIdx.x * blockDim.x + threadIdx.x;
    if (i < N_EDGES) g_rank[i] = atomicAdd(&g_cnt[dst[i]], 1);
}

__global__ void __launch_bounds__(1024) k_scan() {
    const int ITEMS = (N_NODES + 1023) / 1024;   // 49
    int t = threadIdx.x, lane = t & 31, wid = t >> 5;
    int base = t * ITEMS;

    int sum = 0;
#pragma unroll
    for (int i = 0; i < ITEMS; i++) {
        int idx = base + i;
        if (idx < N_NODES) sum += g_cnt[idx];
    }
    int v = sum;
#pragma unroll
    for (int off = 1; off < 32; off <<= 1) {
        int n = __shfl_up_sync(0xffffffffu, v, off);
        if (lane >= off) v += n;
    }
    __shared__ int wsum[32];
    if (lane == 31) wsum[wid] = v;
    __syncthreads();
    if (wid == 0) {
        int w = wsum[lane];
#pragma unroll
        for (int off = 1; off < 32; off <<= 1) {
            int n = __shfl_up_sync(0xffffffffu, w, off);
            if (lane >= off) w += n;
        }
        wsum[lane] = w;
    }
    __syncthreads();
    int excl = v - sum + (wid > 0 ? wsum[wid - 1] : 0);

    int run = excl;
#pragma unroll
    for (int i = 0; i < ITEMS; i++) {
        int idx = base + i;
        if (idx < N_NODES) { g_off[idx] = run; run += g_cnt[idx]; }
    }
    if (t == 0) g_off[N_NODES] = N_EDGES;
}

// atomic-free fill: slot = off[dst] + precomputed rank; also save slot
__global__ void k_fill(const int* __restrict__ src, const int* __restrict__ dst) {
    int i = blockIdx.x * blockDim.x + threadIdx.x;
    if (i >= N_EDGES) return;
    int slot = g_off[dst[i]] + g_rank[i];
    g_csr[slot] = src[i];
    g_slot[i]   = slot;
}

// ===== per-layer edge weights: ex = exp(leaky(s[src]+t[dst]+ab)), CSR order
// (max-subtraction dropped: |e| << 80, exp safe; softmax shift-invariant)
__global__ void k_ex(const int* __restrict__ src, const int* __restrict__ dst,
                     const float* __restrict__ abp) {
    int i = blockIdx.x * blockDim.x + threadIdx.x;
    if (i >= N_EDGES) return;
    float e = g_s[src[i]] + g_t[dst[i]] + abp[0];
    e = e > 0.f ? e : LEAKY * e;
    g_ex[g_slot[i]] = __expf(e);
}

// ============ tensor-core GEMM: z = X @ W^T + b  (bf16 hi/lo split) ========
__device__ __forceinline__ void mma16816(float d[4], const uint32_t a[4],
                                         const uint32_t b[2]) {
    asm volatile(
        "mma.sync.aligned.m16n8k16.row.col.f32.bf16.bf16.f32 "
        "{%0,%1,%2,%3}, {%4,%5,%6,%7}, {%8,%9}, {%0,%1,%2,%3};"
        : "+f"(d[0]), "+f"(d[1]), "+f"(d[2]), "+f"(d[3])
        : "r"(a[0]), "r"(a[1]), "r"(a[2]), "r"(a[3]), "r"(b[0]), "r"(b[1]));
}

#define SSTR 40   // smem K-stride in bf16 elems (80B) -> conflict-free frags

template <int K>
__global__ void __launch_bounds__(256) k_gemm_tc(
    const float* __restrict__ X,          // nullptr -> g_h1
    const float* __restrict__ W,
    const float* __restrict__ bias,
    const float* __restrict__ a)          // length 2*HID
{
    __shared__ __nv_bfloat16 sAh[128][SSTR], sAl[128][SSTR];
    __shared__ __nv_bfloat16 sBh[128][SSTR], sBl[128][SSTR];
    __shared__ float s_part[2][128], t_part[2][128];

    const float* __restrict__ Xp = X ? X : g_h1;

    const int tid   = threadIdx.x;
    const int wid   = tid >> 5;
    const int lane  = tid & 31;
    const int g     = lane >> 2;
    const int tig   = lane & 3;
    const int warpM = wid & 3;
    const int warpN = wid >> 2;
    const int row0  = blockIdx.x * 128;

    float acc[2][8][4];
#pragma unroll
    for (int mt = 0; mt < 2; mt++)
#pragma unroll
        for (int nt = 0; nt < 8; nt++)
#pragma unroll
            for (int r = 0; r < 4; r++) acc[mt][nt][r] = 0.f;

    for (int k0 = 0; k0 < K; k0 += 32) {
#pragma unroll
        for (int v = 0; v < 4; v++) {
            int q  = tid + v * 256;
            int r  = q >> 3;
            int kq = (q & 7) << 2;
            int gr = row0 + r;
            float4 xv = make_float4(0.f, 0.f, 0.f, 0.f);
            if (gr < N_NODES)
                xv = *(const float4*)(Xp + (size_t)gr * K + k0 + kq);
            float4 wv = *(const float4*)(W + (size_t)r * K + k0 + kq);
            const float* xs = &xv.x;
            const float* ws = &wv.x;
#pragma unroll
            for (int i = 0; i < 4; i++) {
                float x = xs[i];
                __nv_bfloat16 hx = __float2bfloat16(x);
                sAh[r][kq + i] = hx;
                sAl[r][kq + i] = __float2bfloat16(x - __bfloat162float(hx));
                float w = ws[i];
                __nv_bfloat16 hw = __float2bfloat16(w);
                sBh[r][kq + i] = hw;
                sBl[r][kq + i] = __float2bfloat16(w - __bfloat162float(hw));
            }
        }
        __syncthreads();

#pragma unroll
        for (int ks = 0; ks < 32; ks += 16) {
            uint32_t ah[2][4], al[2][4];
#pragma unroll
            for (int mt = 0; mt < 2; mt++) {
                int r = warpM * 32 + mt * 16 + g;
                int kk = ks + tig * 2;
                ah[mt][0] = *(const uint32_t*)&sAh[r][kk];
                ah[mt][1] = *(const uint32_t*)&sAh[r + 8][kk];
                ah[mt][2] = *(const uint32_t*)&sAh[r][kk + 8];
                ah[mt][3] = *(const uint32_t*)&sAh[r + 8][kk + 8];
                al[mt][0] = *(const uint32_t*)&sAl[r][kk];
                al[mt][1] = *(const uint32_t*)&sAl[r + 8][kk];
                al[mt][2] = *(const uint32_t*)&sAl[r][kk + 8];
                al[mt][3] = *(const uint32_t*)&sAl[r + 8][kk + 8];
            }
            uint32_t bh[8][2], bl[8][2];
#pragma unroll
            for (int nt = 0; nt < 8; nt++) {
                int c = warpN * 64 + nt * 8 + g;
                int kk = ks + tig * 2;
                bh[nt][0] = *(const uint32_t*)&sBh[c][kk];
                bh[nt][1] = *(const uint32_t*)&sBh[c][kk + 8];
                bl[nt][0] = *(const uint32_t*)&sBl[c][kk];
                bl[nt][1] = *(const uint32_t*)&sBl[c][kk + 8];
            }
#pragma unroll
            for (int mt = 0; mt < 2; mt++)
#pragma unroll
                for (int nt = 0; nt < 8; nt++) {
                    mma16816(acc[mt][nt], ah[mt], bh[nt]);
                    mma16816(acc[mt][nt], ah[mt], bl[nt]);
                    mma16816(acc[mt][nt], al[mt], bh[nt]);
                }
        }
        __syncthreads();
    }

    float sp[2][2] = {{0.f, 0.f}, {0.f, 0.f}};
    float tp[2][2] = {{0.f, 0.f}, {0.f, 0.f}};
#pragma unroll
    for (int mt = 0; mt < 2; mt++) {
        int rA = row0 + warpM * 32 + mt * 16 + g;
        int rB = rA + 8;
#pragma unroll
        for (int nt = 0; nt < 8; nt++) {
            int c0 = warpN * 64 + nt * 8 + tig * 2;
            float bb0 = bias[c0], bb1 = bias[c0 + 1];
            float a0s = a[c0], a1s = a[c0 + 1];
            float a0d = a[HID + c0], a1d = a[HID + c0 + 1];
            float v0 = acc[mt][nt][0] + bb0;
            float v1 = acc[mt][nt][1] + bb1;
            float v2 = acc[mt][nt][2] + bb0;
            float v3 = acc[mt][nt][3] + bb1;
            if (rA < N_NODES)
                g_zh[(size_t)rA * (HID / 2) + (c0 >> 1)] = __floats2half2_rn(v0, v1);
            if (rB < N_NODES)
                g_zh[(size_t)rB * (HID / 2) + (c0 >> 1)] = __floats2half2_rn(v2, v3);
            sp[mt][0] = fmaf(v0, a0s, fmaf(v1, a1s, sp[mt][0]));
            tp[mt][0] = fmaf(v0, a0d, fmaf(v1, a1d, tp[mt][0]));
            sp[mt][1] = fmaf(v2, a0s, fmaf(v3, a1s, sp[mt][1]));
            tp[mt][1] = fmaf(v2, a0d, fmaf(v3, a1d, tp[mt][1]));
        }
    }
#pragma unroll
    for (int mt = 0; mt < 2; mt++)
#pragma unroll
        for (int hh = 0; hh < 2; hh++) {
            float s = sp[mt][hh], t = tp[mt][hh];
            s += __shfl_xor_sync(0xffffffffu, s, 1);
            s += __shfl_xor_sync(0xffffffffu, s, 2);
            t += __shfl_xor_sync(0xffffffffu, t, 1);
            t += __shfl_xor_sync(0xffffffffu, t, 2);
            if (tig == 0) {
                int lr = warpM * 32 + mt * 16 + hh * 8 + g;
                s_part[warpN][lr] = s;
                t_part[warpN][lr] = t;
            }
        }
    __syncthreads();
    if (tid < 128) {
        int gr = row0 + tid;
        if (gr < N_NODES) {
            g_s[gr] = s_part[0][tid] + s_part[1][tid];
            g_t[gr] = t_part[0][tid] + t_part[1][tid];
        }
    }
}

// ======== aggregate: per-dst gather of fp16 z + precomputed ex =============
// One warp per dst node. Chain is just csr -> z(fp16, 256B/row) -> fma;
// ex arrives via parallel broadcast load. x2 unroll. No atomics.
__global__ void __launch_bounds__(256) k_agg(float* __restrict__ out) {
    int node = (blockIdx.x * blockDim.x + threadIdx.x) >> 5;
    if (node >= N_NODES) return;
    int lane = threadIdx.x & 31;
    float* __restrict__ op = out ? out : g_h1;

    int off0 = g_off[node];
    int off1 = g_off[node + 1];

    const uint2* __restrict__ zh = (const uint2*)g_zh;   // 4 halfs per uint2

    float4 acc = make_float4(0.f, 0.f, 0.f, 0.f);
    float  den = 0.f;

    int j = off0;
    for (; j + 2 <= off1; j += 2) {
        int   s0 = g_csr[j];
        int   s1 = g_csr[j + 1];
        float x0 = g_ex[j];
        float x1 = g_ex[j + 1];
        uint2 u0 = zh[(size_t)s0 * 32 + lane];
        uint2 u1 = zh[(size_t)s1 * 32 + lane];
        float2 a0 = __half22float2(*(const __half2*)&u0.x);
        float2 b0 = __half22float2(*(const __half2*)&u0.y);
        float2 a1 = __half22float2(*(const __half2*)&u1.x);
        float2 b1 = __half22float2(*(const __half2*)&u1.y);
        acc.x = fmaf(x0, a0.x, acc.x); acc.y = fmaf(x0, a0.y, acc.y);
        acc.z = fmaf(x0, b0.x, acc.z); acc.w = fmaf(x0, b0.y, acc.w);
        acc.x = fmaf(x1, a1.x, acc.x); acc.y = fmaf(x1, a1.y, acc.y);
        acc.z = fmaf(x1, b1.x, acc.z); acc.w = fmaf(x1, b1.y, acc.w);
        den += x0 + x1;
    }
    if (j < off1) {
        int   s0 = g_csr[j];
        float x0 = g_ex[j];
        uint2 u0 = zh[(size_t)s0 * 32 + lane];
        float2 a0 = __half22float2(*(const __half2*)&u0.x);
        float2 b0 = __half22float2(*(const __half2*)&u0.y);
        acc.x = fmaf(x0, a0.x, acc.x); acc.y = fmaf(x0, a0.y, acc.y);
        acc.z = fmaf(x0, b0.x, acc.z); acc.w = fmaf(x0, b0.y, acc.w);
        den += x0;
    }

    float inv = den > 0.f ? 1.f / den : 0.f;
    float4 r;
    r.x = elu1(acc.x * inv);
    r.y = elu1(acc.y * inv);
    r.z = elu1(acc.z * inv);
    r.w = elu1(acc.w * inv);
    *(float4*)(&op[(size_t)node * HID + lane * 4]) = r;
}

// ---------------- launch ----------------
extern "C" void kernel_launch(void* const* d_in, const int* in_sizes, int n_in,
                              void* d_out, int out_size) {
    const float* h   = (const float*)d_in[0];
    const int*   src = (const int*)d_in[1];
    const int*   dst = (const int*)d_in[2];
    const float* W1  = (const float*)d_in[3];
    const float* b1  = (const float*)d_in[4];
    const float* a1  = (const float*)d_in[5];
    const float* ab1 = (const float*)d_in[6];
    const float* W2  = (const float*)d_in[7];
    const float* b2  = (const float*)d_in[8];
    const float* a2  = (const float*)d_in[9];
    const float* ab2 = (const float*)d_in[10];
    float* out = (float*)d_out;

    const int zeroB = (N_NODES + 255) / 256;
    const int edgeB = (N_EDGES + 255) / 256;
    const int gemmB = (N_NODES + 127) / 128;
    const int aggB  = (N_NODES * 32 + 255) / 256;

    // ---- CSR build (shared by both layers) ----
    k_zero<<<zeroB, 256>>>();
    k_hist<<<edgeB, 256>>>(dst);
    k_scan<<<1, 1024>>>();
    k_fill<<<edgeB, 256>>>(src, dst);

    // ---- layer 1 ----
    k_gemm_tc<IN_DIM><<<gemmB, 256>>>(h, W1, b1, a1);
    k_ex<<<edgeB, 256>>>(src, dst, ab1);
    k_agg<<<aggB, 256>>>(nullptr);             // -> g_h1 (ELU applied)

    // ---- layer 2 ----
    k_gemm_tc<HID><<<gemmB, 256>>>(nullptr, W2, b2, a2);   // X = g_h1
    k_ex<<<edgeB, 256>>>(src, dst, ab2);
    k_agg<<<aggB, 256>>>(out);
}

// round 10
// speedup vs baseline: 1.0531x; 1.0531x over previous
#include <cuda_runtime.h>
#include <cuda_bf16.h>
#include <cuda_fp16.h>
#include <cstdint>

#define N_NODES 50000
#define N_EDGES 800000
#define IN_DIM  256
#define HID     128
#define LEAKY   0.01f

// ---------------- scratch (static device allocations only) ----------------
__device__ __align__(16) __half2 g_zh[N_NODES * (HID / 2)]; // fc output, fp16
__device__ __align__(16) float g_h1[N_NODES * HID];    // layer-1 result (ELU)
__device__ float g_s[N_NODES];                          // z . a[:D]
__device__ float g_t[N_NODES];                          // z . a[D:]
__device__ int   g_cnt[N_NODES];                        // in-degree histogram
__device__ int   g_rank[N_EDGES];                       // edge rank within dst seg
__device__ int   g_slot[N_EDGES];                       // CSR slot per edge
__device__ int   g_off[N_NODES + 1];                    // CSR offsets
__device__ int   g_csr[N_EDGES];                        // src id per CSR slot
__device__ float g_ex[N_EDGES];                         // exp(leaky(e)) per slot

__device__ __forceinline__ float elu1(float x) {
    return x > 0.f ? x : (__expf(x) - 1.f);
}

// ================= CSR build (once per call, reused by both layers) ========
__global__ void k_zero() {
    int i = blockIdx.x * blockDim.x + threadIdx.x;
    if (i < N_NODES) g_cnt[i] = 0;
}

// histogram; atomic return value = this edge's rank within its dst segment
__global__ void k_hist(const int* __restrict__ dst) {
    int i = blockIdx.x * blockDim.x + threadIdx.x;
    if (i < N_EDGES) g_rank[i] = atomicAdd(&g_cnt[dst[i]], 1);
}

__global__ void __launch_bounds__(1024) k_scan() {
    const int ITEMS = (N_NODES + 1023) / 1024;   // 49
    int t = threadIdx.x, lane = t & 31, wid = t >> 5;
    int base = t * ITEMS;

    int sum = 0;
#pragma unroll
    for (int i = 0; i < ITEMS; i++) {
        int idx = base + i;
        if (idx < N_NODES) sum += g_cnt[idx];
    }
    int v = sum;
#pragma unroll
    for (int off = 1; off < 32; off <<= 1) {
        int n = __shfl_up_sync(0xffffffffu, v, off);
        if (lane >= off) v += n;
    }
    __shared__ int wsum[32];
    if (lane == 31) wsum[wid] = v;
    __syncthreads();
    if (wid == 0) {
        int w = wsum[lane];
#pragma unroll
        for (int off = 1; off < 32; off <<= 1) {
            int n = __shfl_up_sync(0xffffffffu, w, off);
            if (lane >= off) w += n;
        }
        wsum[lane] = w;
    }
    __syncthreads();
    int excl = v - sum + (wid > 0 ? wsum[wid - 1] : 0);

    int run = excl;
#pragma unroll
    for (int i = 0; i < ITEMS; i++) {
        int idx = base + i;
        if (idx < N_NODES) { g_off[idx] = run; run += g_cnt[idx]; }
    }
    if (t == 0) g_off[N_NODES] = N_EDGES;
}

// atomic-free fill: slot = off[dst] + precomputed rank; also save slot
__global__ void k_fill(const int* __restrict__ src, const int* __restrict__ dst) {
    int i = blockIdx.x * blockDim.x + threadIdx.x;
    if (i >= N_EDGES) return;
    int slot = g_off[dst[i]] + g_rank[i];
    g_csr[slot] = src[i];
    g_slot[i]   = slot;
}

// ===== per-layer edge weights: ex = exp(leaky(s[src]+t[dst]+ab)), CSR order
// (max-subtraction dropped: |e| << 80, exp safe; softmax shift-invariant)
__global__ void k_ex(const int* __restrict__ src, const int* __restrict__ dst,
                     const float* __restrict__ abp) {
    int i = blockIdx.x * blockDim.x + threadIdx.x;
    if (i >= N_EDGES) return;
    float e = g_s[src[i]] + g_t[dst[i]] + abp[0];
    e = e > 0.f ? e : LEAKY * e;
    g_ex[g_slot[i]] = __expf(e);
}

// ============ tensor-core GEMM: z = X @ W^T + b  (bf16 hi/lo split) ========
__device__ __forceinline__ void mma16816(float d[4], const uint32_t a[4],
                                         const uint32_t b[2]) {
    asm volatile(
        "mma.sync.aligned.m16n8k16.row.col.f32.bf16.bf16.f32 "
        "{%0,%1,%2,%3}, {%4,%5,%6,%7}, {%8,%9}, {%0,%1,%2,%3};"
        : "+f"(d[0]), "+f"(d[1]), "+f"(d[2]), "+f"(d[3])
        : "r"(a[0]), "r"(a[1]), "r"(a[2]), "r"(a[3]), "r"(b[0]), "r"(b[1]));
}

#define SSTR 40   // smem K-stride in bf16 elems (80B) -> conflict-free frags

template <int K>
__global__ void __launch_bounds__(256) k_gemm_tc(
    const float* __restrict__ X,          // nullptr -> g_h1
    const float* __restrict__ W,
    const float* __restrict__ bias,
    const float* __restrict__ a)          // length 2*HID
{
    __shared__ __nv_bfloat16 sAh[128][SSTR], sAl[128][SSTR];
    __shared__ __nv_bfloat16 sBh[128][SSTR], sBl[128][SSTR];
    __shared__ float s_part[2][128], t_part[2][128];

    const float* __restrict__ Xp = X ? X : g_h1;

    const int tid   = threadIdx.x;
    const int wid   = tid >> 5;
    const int lane  = tid & 31;
    const int g     = lane >> 2;
    const int tig   = lane & 3;
    const int warpM = wid & 3;
    const int warpN = wid >> 2;
    const int row0  = blockIdx.x * 128;

    float acc[2][8][4];
#pragma unroll
    for (int mt = 0; mt < 2; mt++)
#pragma unroll
        for (int nt = 0; nt < 8; nt++)
#pragma unroll
            for (int r = 0; r < 4; r++) acc[mt][nt][r] = 0.f;

    for (int k0 = 0; k0 < K; k0 += 32) {
#pragma unroll
        for (int v = 0; v < 4; v++) {
            int q  = tid + v * 256;
            int r  = q >> 3;
            int kq = (q & 7) << 2;
            int gr = row0 + r;
            float4 xv = make_float4(0.f, 0.f, 0.f, 0.f);
            if (gr < N_NODES)
                xv = *(const float4*)(Xp + (size_t)gr * K + k0 + kq);
            float4 wv = *(const float4*)(W + (size_t)r * K + k0 + kq);
            const float* xs = &xv.x;
            const float* ws = &wv.x;
#pragma unroll
            for (int i = 0; i < 4; i++) {
                float x = xs[i];
                __nv_bfloat16 hx = __float2bfloat16(x);
                sAh[r][kq + i] = hx;
                sAl[r][kq + i] = __float2bfloat16(x - __bfloat162float(hx));
                float w = ws[i];
                __nv_bfloat16 hw = __float2bfloat16(w);
                sBh[r][kq + i] = hw;
                sBl[r][kq + i] = __float2bfloat16(w - __bfloat162float(hw));
            }
        }
        __syncthreads();

#pragma unroll
        for (int ks = 0; ks < 32; ks += 16) {
            uint32_t ah[2][4], al[2][4];
#pragma unroll
            for (int mt = 0; mt < 2; mt++) {
                int r = warpM * 32 + mt * 16 + g;
                int kk = ks + tig * 2;
                ah[mt][0] = *(const uint32_t*)&sAh[r][kk];
                ah[mt][1] = *(const uint32_t*)&sAh[r + 8][kk];
                ah[mt][2] = *(const uint32_t*)&sAh[r][kk + 8];
                ah[mt][3] = *(const uint32_t*)&sAh[r + 8][kk + 8];
                al[mt][0] = *(const uint32_t*)&sAl[r][kk];
                al[mt][1] = *(const uint32_t*)&sAl[r + 8][kk];
                al[mt][2] = *(const uint32_t*)&sAl[r][kk + 8];
                al[mt][3] = *(const uint32_t*)&sAl[r + 8][kk + 8];
            }
            uint32_t bh[8][2], bl[8][2];
#pragma unroll
            for (int nt = 0; nt < 8; nt++) {
                int c = warpN * 64 + nt * 8 + g;
                int kk = ks + tig * 2;
                bh[nt][0] = *(const uint32_t*)&sBh[c][kk];
                bh[nt][1] = *(const uint32_t*)&sBh[c][kk + 8];
                bl[nt][0] = *(const uint32_t*)&sBl[c][kk];
                bl[nt][1] = *(const uint32_t*)&sBl[c][kk + 8];
            }
#pragma unroll
            for (int mt = 0; mt < 2; mt++)
#pragma unroll
                for (int nt = 0; nt < 8; nt++) {
                    mma16816(acc[mt][nt], ah[mt], bh[nt]);
                    mma16816(acc[mt][nt], ah[mt], bl[nt]);
                    mma16816(acc[mt][nt], al[mt], bh[nt]);
                }
        }
        __syncthreads();
    }

    float sp[2][2] = {{0.f, 0.f}, {0.f, 0.f}};
    float tp[2][2] = {{0.f, 0.f}, {0.f, 0.f}};
#pragma unroll
    for (int mt = 0; mt < 2; mt++) {
        int rA = row0 + warpM * 32 + mt * 16 + g;
        int rB = rA + 8;
#pragma unroll
        for (int nt = 0; nt < 8; nt++) {
            int c0 = warpN * 64 + nt * 8 + tig * 2;
            float bb0 = bias[c0], bb1 = bias[c0 + 1];
            float a0s = a[c0], a1s = a[c0 + 1];
            float a0d = a[HID + c0], a1d = a[HID + c0 + 1];
            float v0 = acc[mt][nt][0] + bb0;
            float v1 = acc[mt][nt][1] + bb1;
            float v2 = acc[mt][nt][2] + bb0;
            float v3 = acc[mt][nt][3] + bb1;
            if (rA < N_NODES)
                g_zh[(size_t)rA * (HID / 2) + (c0 >> 1)] = __floats2half2_rn(v0, v1);
            if (rB < N_NODES)
                g_zh[(size_t)rB * (HID / 2) + (c0 >> 1)] = __floats2half2_rn(v2, v3);
            sp[mt][0] = fmaf(v0, a0s, fmaf(v1, a1s, sp[mt][0]));
            tp[mt][0] = fmaf(v0, a0d, fmaf(v1, a1d, tp[mt][0]));
            sp[mt][1] = fmaf(v2, a0s, fmaf(v3, a1s, sp[mt][1]));
            tp[mt][1] = fmaf(v2, a0d, fmaf(v3, a1d, tp[mt][1]));
        }
    }
#pragma unroll
    for (int mt = 0; mt < 2; mt++)
#pragma unroll
        for (int hh = 0; hh < 2; hh++) {
            float s = sp[mt][hh], t = tp[mt][hh];
            s += __shfl_xor_sync(0xffffffffu, s, 1);
            s += __shfl_xor_sync(0xffffffffu, s, 2);
            t += __shfl_xor_sync(0xffffffffu, t, 1);
            t += __shfl_xor_sync(0xffffffffu, t, 2);
            if (tig == 0) {
                int lr = warpM * 32 + mt * 16 + hh * 8 + g;
                s_part[warpN][lr] = s;
                t_part[warpN][lr] = t;
            }
        }
    __syncthreads();
    if (tid < 128) {
        int gr = row0 + tid;
        if (gr < N_NODES) {
            g_s[gr] = s_part[0][tid] + s_part[1][tid];
            g_t[gr] = t_part[0][tid] + t_part[1][tid];
        }
    }
}

// ======== aggregate: software-pipelined per-dst gather =====================
// One warp per dst node. Iter i's z-loads overlap iter i+1's csr/ex loads.
// Out-of-range edges read row 0 with weight 0 (harmless). No atomics.
__global__ void __launch_bounds__(256) k_agg(float* __restrict__ out) {
    int node = (blockIdx.x * blockDim.x + threadIdx.x) >> 5;
    if (node >= N_NODES) return;
    int lane = threadIdx.x & 31;
    float* __restrict__ op = out ? out : g_h1;

    int off0 = g_off[node];
    int off1 = g_off[node + 1];

    const uint2* __restrict__ zh = (const uint2*)g_zh;   // 4 halfs per uint2

    float4 acc = make_float4(0.f, 0.f, 0.f, 0.f);
    float  den = 0.f;

    // prologue: preload first pair of (csr, ex)
    int   sA = 0, sB = 0;
    float xA = 0.f, xB = 0.f;
    if (off0 < off1)     { sA = g_csr[off0];     xA = g_ex[off0]; }
    if (off0 + 1 < off1) { sB = g_csr[off0 + 1]; xB = g_ex[off0 + 1]; }

    for (int j = off0; j < off1; j += 2) {
        int   s0 = sA, s1 = sB;
        float x0 = xA, x1 = xB;

        // preload next pair (overlaps with this iter's z loads)
        int jn = j + 2;
        sA = 0; sB = 0; xA = 0.f; xB = 0.f;
        if (jn < off1)     { sA = g_csr[jn];     xA = g_ex[jn]; }
        if (jn + 1 < off1) { sB = g_csr[jn + 1]; xB = g_ex[jn + 1]; }

        uint2 u0 = zh[(size_t)s0 * 32 + lane];
        uint2 u1 = zh[(size_t)s1 * 32 + lane];
        float2 a0 = __half22float2(*(const __half2*)&u0.x);
        float2 b0 = __half22float2(*(const __half2*)&u0.y);
        float2 a1 = __half22float2(*(const __half2*)&u1.x);
        float2 b1 = __half22float2(*(const __half2*)&u1.y);
        acc.x = fmaf(x0, a0.x, acc.x); acc.y = fmaf(x0, a0.y, acc.y);
        acc.z = fmaf(x0, b0.x, acc.z); acc.w = fmaf(x0, b0.y, acc.w);
        acc.x = fmaf(x1, a1.x, acc.x); acc.y = fmaf(x1, a1.y, acc.y);
        acc.z = fmaf(x1, b1.x, acc.z); acc.w = fmaf(x1, b1.y, acc.w);
        den += x0 + x1;
    }

    float inv = den > 0.f ? 1.f / den : 0.f;
    float4 r;
    r.x = elu1(acc.x * inv);
    r.y = elu1(acc.y * inv);
    r.z = elu1(acc.z * inv);
    r.w = elu1(acc.w * inv);
    *(float4*)(&op[(size_t)node * HID + lane * 4]) = r;
}

// ---------------- launch ----------------
extern "C" void kernel_launch(void* const* d_in, const int* in_sizes, int n_in,
                              void* d_out, int out_size) {
    const float* h   = (const float*)d_in[0];
    const int*   src = (const int*)d_in[1];
    const int*   dst = (const int*)d_in[2];
    const float* W1  = (const float*)d_in[3];
    const float* b1  = (const float*)d_in[4];
    const float* a1  = (const float*)d_in[5];
    const float* ab1 = (const float*)d_in[6];
    const float* W2  = (const float*)d_in[7];
    const float* b2  = (const float*)d_in[8];
    const float* a2  = (const float*)d_in[9];
    const float* ab2 = (const float*)d_in[10];
    float* out = (float*)d_out;

    const int zeroB = (N_NODES + 255) / 256;
    const int edgeB = (N_EDGES + 255) / 256;
    const int gemmB = (N_NODES + 127) / 128;
    const int aggB  = (N_NODES * 32 + 255) / 256;

    // Side stream + events for fork/join (created per call; graph capture
    // turns record/wait into graph edges). Not destroyed: destroying during
    // an active capture would invalidate it, and only a few calls occur.
    cudaStream_t s2;
    cudaStreamCreateWithFlags(&s2, cudaStreamNonBlocking);
    cudaEvent_t evFork, evJoin;
    cudaEventCreateWithFlags(&evFork, cudaEventDisableTiming);
    cudaEventCreateWithFlags(&evJoin, cudaEventDisableTiming);

    // ---- fork: CSR build (s2) overlaps GEMM-1 (default stream) ----
    cudaEventRecord(evFork, 0);
    cudaStreamWaitEvent(s2, evFork, 0);

    k_gemm_tc<IN_DIM><<<gemmB, 256>>>(h, W1, b1, a1);   // default stream

    k_zero<<<zeroB, 256, 0, s2>>>();
    k_hist<<<edgeB, 256, 0, s2>>>(dst);
    k_scan<<<1, 1024, 0, s2>>>();
    k_fill<<<edgeB, 256, 0, s2>>>(src, dst);

    cudaEventRecord(evJoin, s2);
    cudaStreamWaitEvent(0, evJoin, 0);

    // ---- layer 1 edge phase ----
    k_ex<<<edgeB, 256>>>(src, dst, ab1);
    k_agg<<<aggB, 256>>>(nullptr);             // -> g_h1 (ELU applied)

    // ---- layer 2 ----
    k_gemm_tc<HID><<<gemmB, 256>>>(nullptr, W2, b2, a2);   // X = g_h1
    k_ex<<<edgeB, 256>>>(src, dst, ab2);
    k_agg<<<aggB, 256>>>(out);
}

// round 11
// speedup vs baseline: 1.3246x; 1.2577x over previous
#include <cuda_runtime.h>
#include <cuda_bf16.h>
#include <cuda_fp16.h>
#include <cstdint>

#define N_NODES 50000
#define N_EDGES 800000
#define IN_DIM  256
#define HID     128
#define LEAKY   0.01f

#define SCAN_B  1024
#define SCAN_NB ((N_NODES + SCAN_B - 1) / SCAN_B)   // 49

// ---------------- scratch (static device allocations only) ----------------
__device__ __align__(16) __half2 g_zh[N_NODES * (HID / 2)]; // fc output, fp16
__device__ __align__(16) float g_h1[N_NODES * HID];    // layer-1 result (ELU)
__device__ float g_s[N_NODES];                          // z . a[:D]
__device__ float g_t[N_NODES];                          // z . a[D:]
__device__ int   g_cnt[N_NODES];                        // in-degree histogram
__device__ int   g_rank[N_EDGES];                       // edge rank within dst seg
__device__ int   g_slot[N_EDGES];                       // CSR slot per edge
__device__ int   g_off[N_NODES + 1];                    // CSR offsets
__device__ int   g_csr[N_EDGES];                        // src id per CSR slot
__device__ float g_ex[N_EDGES];                         // exp(leaky(e)) per slot
__device__ int   g_locpre[SCAN_NB * SCAN_B];            // block-local ex-prefix
__device__ int   g_bsum[SCAN_NB];                       // per-block totals
__device__ int   g_bpre[SCAN_NB];                       // block prefix (excl)

__device__ __forceinline__ float elu1(float x) {
    return x > 0.f ? x : (__expf(x) - 1.f);
}

// ================= CSR build (once per call, reused by both layers) ========
__global__ void k_zero() {
    int i = blockIdx.x * blockDim.x + threadIdx.x;
    if (i < N_NODES) g_cnt[i] = 0;
}

// histogram; atomic return value = this edge's rank within its dst segment
__global__ void k_hist(const int* __restrict__ dst) {
    int i = blockIdx.x * blockDim.x + threadIdx.x;
    if (i < N_EDGES) g_rank[i] = atomicAdd(&g_cnt[dst[i]], 1);
}

// --- hierarchical scan: A) block-local scan, B) scan block sums, C) add ---
__global__ void __launch_bounds__(SCAN_B) k_scanA() {
    int t = threadIdx.x, lane = t & 31, wid = t >> 5;
    int i = blockIdx.x * SCAN_B + t;
    int v = (i < N_NODES) ? g_cnt[i] : 0;

    int inc = v;
#pragma unroll
    for (int off = 1; off < 32; off <<= 1) {
        int n = __shfl_up_sync(0xffffffffu, inc, off);
        if (lane >= off) inc += n;
    }
    __shared__ int wsum[32];
    if (lane == 31) wsum[wid] = inc;
    __syncthreads();
    if (wid == 0) {
        int w = wsum[lane];
#pragma unroll
        for (int off = 1; off < 32; off <<= 1) {
            int n = __shfl_up_sync(0xffffffffu, w, off);
            if (lane >= off) w += n;
        }
        wsum[lane] = w;
    }
    __syncthreads();
    int incl = inc + (wid > 0 ? wsum[wid - 1] : 0);
    g_locpre[blockIdx.x * SCAN_B + t] = incl - v;       // exclusive
    if (t == SCAN_B - 1) g_bsum[blockIdx.x] = incl;     // block total
}

__global__ void k_scanB() {     // one warp; 2 items/lane covers 49 blocks
    int lane = threadIdx.x;
    int v0 = (2 * lane     < SCAN_NB) ? g_bsum[2 * lane]     : 0;
    int v1 = (2 * lane + 1 < SCAN_NB) ? g_bsum[2 * lane + 1] : 0;
    int s  = v0 + v1;
    int inc = s;
#pragma unroll
    for (int off = 1; off < 32; off <<= 1) {
        int n = __shfl_up_sync(0xffffffffu, inc, off);
        if (lane >= off) inc += n;
    }
    int excl = inc - s;
    if (2 * lane     < SCAN_NB) g_bpre[2 * lane]     = excl;
    if (2 * lane + 1 < SCAN_NB) g_bpre[2 * lane + 1] = excl + v0;
}

__global__ void __launch_bounds__(SCAN_B) k_scanC() {
    int i = blockIdx.x * SCAN_B + threadIdx.x;
    if (i < N_NODES)
        g_off[i] = g_locpre[i] + g_bpre[blockIdx.x];
    if (i == 0) g_off[N_NODES] = N_EDGES;
}

// atomic-free fill: slot = off[dst] + precomputed rank; also save slot
__global__ void k_fill(const int* __restrict__ src, const int* __restrict__ dst) {
    int i = blockIdx.x * blockDim.x + threadIdx.x;
    if (i >= N_EDGES) return;
    int slot = g_off[dst[i]] + g_rank[i];
    g_csr[slot] = src[i];
    g_slot[i]   = slot;
}

// ===== per-layer edge weights: ex = exp(leaky(s[src]+t[dst]+ab)), CSR order
// (max-subtraction dropped: |e| << 80, exp safe; softmax shift-invariant)
__global__ void k_ex(const int* __restrict__ src, const int* __restrict__ dst,
                     const float* __restrict__ abp) {
    int i = blockIdx.x * blockDim.x + threadIdx.x;
    if (i >= N_EDGES) return;
    float e = g_s[src[i]] + g_t[dst[i]] + abp[0];
    e = e > 0.f ? e : LEAKY * e;
    g_ex[g_slot[i]] = __expf(e);
}

// ============ tensor-core GEMM: z = X @ W^T + b  (bf16 hi/lo split) ========
__device__ __forceinline__ void mma16816(float d[4], const uint32_t a[4],
                                         const uint32_t b[2]) {
    asm volatile(
        "mma.sync.aligned.m16n8k16.row.col.f32.bf16.bf16.f32 "
        "{%0,%1,%2,%3}, {%4,%5,%6,%7}, {%8,%9}, {%0,%1,%2,%3};"
        : "+f"(d[0]), "+f"(d[1]), "+f"(d[2]), "+f"(d[3])
        : "r"(a[0]), "r"(a[1]), "r"(a[2]), "r"(a[3]), "r"(b[0]), "r"(b[1]));
}

#define SSTR 40   // smem K-stride in bf16 elems (80B) -> conflict-free frags

template <int K>
__global__ void __launch_bounds__(256) k_gemm_tc(
    const float* __restrict__ X,          // nullptr -> g_h1
    const float* __restrict__ W,
    const float* __restrict__ bias,
    const float* __restrict__ a)          // length 2*HID
{
    __shared__ __nv_bfloat16 sAh[128][SSTR], sAl[128][SSTR];
    __shared__ __nv_bfloat16 sBh[128][SSTR], sBl[128][SSTR];
    __shared__ float s_part[2][128], t_part[2][128];

    const float* __restrict__ Xp = X ? X : g_h1;

    const int tid   = threadIdx.x;
    const int wid   = tid >> 5;
    const int lane  = tid & 31;
    const int g     = lane >> 2;
    const int tig   = lane & 3;
    const int warpM = wid & 3;
    const int warpN = wid >> 2;
    const int row0  = blockIdx.x * 128;

    float acc[2][8][4];
#pragma unroll
    for (int mt = 0; mt < 2; mt++)
#pragma unroll
        for (int nt = 0; nt < 8; nt++)
#pragma unroll
            for (int r = 0; r < 4; r++) acc[mt][nt][r] = 0.f;

    for (int k0 = 0; k0 < K; k0 += 32) {
#pragma unroll
        for (int v = 0; v < 4; v++) {
            int q  = tid + v * 256;
            int r  = q >> 3;
            int kq = (q & 7) << 2;
            int gr = row0 + r;
            float4 xv = make_float4(0.f, 0.f, 0.f, 0.f);
            if (gr < N_NODES)
                xv = *(const float4*)(Xp + (size_t)gr * K + k0 + kq);
            float4 wv = *(const float4*)(W + (size_t)r * K + k0 + kq);
            const float* xs = &xv.x;
            const float* ws = &wv.x;
#pragma unroll
            for (int i = 0; i < 4; i++) {
                float x = xs[i];
                __nv_bfloat16 hx = __float2bfloat16(x);
                sAh[r][kq + i] = hx;
                sAl[r][kq + i] = __float2bfloat16(x - __bfloat162float(hx));
                float w = ws[i];
                __nv_bfloat16 hw = __float2bfloat16(w);
                sBh[r][kq + i] = hw;
                sBl[r][kq + i] = __float2bfloat16(w - __bfloat162float(hw));
            }
        }
        __syncthreads();

#pragma unroll
        for (int ks = 0; ks < 32; ks += 16) {
            uint32_t ah[2][4], al[2][4];
#pragma unroll
            for (int mt = 0; mt < 2; mt++) {
                int r = warpM * 32 + mt * 16 + g;
                int kk = ks + tig * 2;
                ah[mt][0] = *(const uint32_t*)&sAh[r][kk];
                ah[mt][1] = *(const uint32_t*)&sAh[r + 8][kk];
                ah[mt][2] = *(const uint32_t*)&sAh[r][kk + 8];
                ah[mt][3] = *(const uint32_t*)&sAh[r + 8][kk + 8];
                al[mt][0] = *(const uint32_t*)&sAl[r][kk];
                al[mt][1] = *(const uint32_t*)&sAl[r + 8][kk];
                al[mt][2] = *(const uint32_t*)&sAl[r][kk + 8];
                al[mt][3] = *(const uint32_t*)&sAl[r + 8][kk + 8];
            }
            uint32_t bh[8][2], bl[8][2];
#pragma unroll
            for (int nt = 0; nt < 8; nt++) {
                int c = warpN * 64 + nt * 8 + g;
                int kk = ks + tig * 2;
                bh[nt][0] = *(const uint32_t*)&sBh[c][kk];
                bh[nt][1] = *(const uint32_t*)&sBh[c][kk + 8];
                bl[nt][0] = *(const uint32_t*)&sBl[c][kk];
                bl[nt][1] = *(const uint32_t*)&sBl[c][kk + 8];
            }
#pragma unroll
            for (int mt = 0; mt < 2; mt++)
#pragma unroll
                for (int nt = 0; nt < 8; nt++) {
                    mma16816(acc[mt][nt], ah[mt], bh[nt]);
                    mma16816(acc[mt][nt], ah[mt], bl[nt]);
                    mma16816(acc[mt][nt], al[mt], bh[nt]);
                }
        }
        __syncthreads();
    }

    float sp[2][2] = {{0.f, 0.f}, {0.f, 0.f}};
    float tp[2][2] = {{0.f, 0.f}, {0.f, 0.f}};
#pragma unroll
    for (int mt = 0; mt < 2; mt++) {
        int rA = row0 + warpM * 32 + mt * 16 + g;
        int rB = rA + 8;
#pragma unroll
        for (int nt = 0; nt < 8; nt++) {
            int c0 = warpN * 64 + nt * 8 + tig * 2;
            float bb0 = bias[c0], bb1 = bias[c0 + 1];
            float a0s = a[c0], a1s = a[c0 + 1];
            float a0d = a[HID + c0], a1d = a[HID + c0 + 1];
            float v0 = acc[mt][nt][0] + bb0;
            float v1 = acc[mt][nt][1] + bb1;
            float v2 = acc[mt][nt][2] + bb0;
            float v3 = acc[mt][nt][3] + bb1;
            if (rA < N_NODES)
                g_zh[(size_t)rA * (HID / 2) + (c0 >> 1)] = __floats2half2_rn(v0, v1);
            if (rB < N_NODES)
                g_zh[(size_t)rB * (HID / 2) + (c0 >> 1)] = __floats2half2_rn(v2, v3);
            sp[mt][0] = fmaf(v0, a0s, fmaf(v1, a1s, sp[mt][0]));
            tp[mt][0] = fmaf(v0, a0d, fmaf(v1, a1d, tp[mt][0]));
            sp[mt][1] = fmaf(v2, a0s, fmaf(v3, a1s, sp[mt][1]));
            tp[mt][1] = fmaf(v2, a0d, fmaf(v3, a1d, tp[mt][1]));
        }
    }
#pragma unroll
    for (int mt = 0; mt < 2; mt++)
#pragma unroll
        for (int hh = 0; hh < 2; hh++) {
            float s = sp[mt][hh], t = tp[mt][hh];
            s += __shfl_xor_sync(0xffffffffu, s, 1);
            s += __shfl_xor_sync(0xffffffffu, s, 2);
            t += __shfl_xor_sync(0xffffffffu, t, 1);
            t += __shfl_xor_sync(0xffffffffu, t, 2);
            if (tig == 0) {
                int lr = warpM * 32 + mt * 16 + hh * 8 + g;
                s_part[warpN][lr] = s;
                t_part[warpN][lr] = t;
            }
        }
    __syncthreads();
    if (tid < 128) {
        int gr = row0 + tid;
        if (gr < N_NODES) {
            g_s[gr] = s_part[0][tid] + s_part[1][tid];
            g_t[gr] = t_part[0][tid] + t_part[1][tid];
        }
    }
}

// ======== aggregate: software-pipelined per-dst gather =====================
// One warp per dst node. Iter i's z-loads overlap iter i+1's csr/ex loads.
// Out-of-range edges read row 0 with weight 0 (harmless). No atomics.
__global__ void __launch_bounds__(256) k_agg(float* __restrict__ out) {
    int node = (blockIdx.x * blockDim.x + threadIdx.x) >> 5;
    if (node >= N_NODES) return;
    int lane = threadIdx.x & 31;
    float* __restrict__ op = out ? out : g_h1;

    int off0 = g_off[node];
    int off1 = g_off[node + 1];

    const uint2* __restrict__ zh = (const uint2*)g_zh;   // 4 halfs per uint2

    float4 acc = make_float4(0.f, 0.f, 0.f, 0.f);
    float  den = 0.f;

    // prologue: preload first pair of (csr, ex)
    int   sA = 0, sB = 0;
    float xA = 0.f, xB = 0.f;
    if (off0 < off1)     { sA = g_csr[off0];     xA = g_ex[off0]; }
    if (off0 + 1 < off1) { sB = g_csr[off0 + 1]; xB = g_ex[off0 + 1]; }

    for (int j = off0; j < off1; j += 2) {
        int   s0 = sA, s1 = sB;
        float x0 = xA, x1 = xB;

        // preload next pair (overlaps with this iter's z loads)
        int jn = j + 2;
        sA = 0; sB = 0; xA = 0.f; xB = 0.f;
        if (jn < off1)     { sA = g_csr[jn];     xA = g_ex[jn]; }
        if (jn + 1 < off1) { sB = g_csr[jn + 1]; xB = g_ex[jn + 1]; }

        uint2 u0 = zh[(size_t)s0 * 32 + lane];
        uint2 u1 = zh[(size_t)s1 * 32 + lane];
        float2 a0 = __half22float2(*(const __half2*)&u0.x);
        float2 b0 = __half22float2(*(const __half2*)&u0.y);
        float2 a1 = __half22float2(*(const __half2*)&u1.x);
        float2 b1 = __half22float2(*(const __half2*)&u1.y);
        acc.x = fmaf(x0, a0.x, acc.x); acc.y = fmaf(x0, a0.y, acc.y);
        acc.z = fmaf(x0, b0.x, acc.z); acc.w = fmaf(x0, b0.y, acc.w);
        acc.x = fmaf(x1, a1.x, acc.x); acc.y = fmaf(x1, a1.y, acc.y);
        acc.z = fmaf(x1, b1.x, acc.z); acc.w = fmaf(x1, b1.y, acc.w);
        den += x0 + x1;
    }

    float inv = den > 0.f ? 1.f / den : 0.f;
    float4 r;
    r.x = elu1(acc.x * inv);
    r.y = elu1(acc.y * inv);
    r.z = elu1(acc.z * inv);
    r.w = elu1(acc.w * inv);
    *(float4*)(&op[(size_t)node * HID + lane * 4]) = r;
}

// ---------------- launch ----------------
extern "C" void kernel_launch(void* const* d_in, const int* in_sizes, int n_in,
                              void* d_out, int out_size) {
    const float* h   = (const float*)d_in[0];
    const int*   src = (const int*)d_in[1];
    const int*   dst = (const int*)d_in[2];
    const float* W1  = (const float*)d_in[3];
    const float* b1  = (const float*)d_in[4];
    const float* a1  = (const float*)d_in[5];
    const float* ab1 = (const float*)d_in[6];
    const float* W2  = (const float*)d_in[7];
    const float* b2  = (const float*)d_in[8];
    const float* a2  = (const float*)d_in[9];
    const float* ab2 = (const float*)d_in[10];
    float* out = (float*)d_out;

    const int zeroB = (N_NODES + 255) / 256;
    const int edgeB = (N_EDGES + 255) / 256;
    const int gemmB = (N_NODES + 127) / 128;
    const int aggB  = (N_NODES * 32 + 255) / 256;

    // Side stream + events for fork/join (created per call; graph capture
    // turns record/wait into graph edges).
    cudaStream_t s2;
    cudaStreamCreateWithFlags(&s2, cudaStreamNonBlocking);
    cudaEvent_t evFork, evJoin;
    cudaEventCreateWithFlags(&evFork, cudaEventDisableTiming);
    cudaEventCreateWithFlags(&evJoin, cudaEventDisableTiming);

    // ---- fork: CSR build (s2) overlaps GEMM-1 (default stream) ----
    cudaEventRecord(evFork, 0);
    cudaStreamWaitEvent(s2, evFork, 0);

    k_gemm_tc<IN_DIM><<<gemmB, 256>>>(h, W1, b1, a1);   // default stream

    k_zero<<<zeroB, 256, 0, s2>>>();
    k_hist<<<edgeB, 256, 0, s2>>>(dst);
    k_scanA<<<SCAN_NB, SCAN_B, 0, s2>>>();
    k_scanB<<<1, 32, 0, s2>>>();
    k_scanC<<<SCAN_NB, SCAN_B, 0, s2>>>();
    k_fill<<<edgeB, 256, 0, s2>>>(src, dst);

    cudaEventRecord(evJoin, s2);
    cudaStreamWaitEvent(0, evJoin, 0);

    // ---- layer 1 edge phase ----
    k_ex<<<edgeB, 256>>>(src, dst, ab1);
    k_agg<<<aggB, 256>>>(nullptr);             // -> g_h1 (ELU applied)

    // ---- layer 2 ----
    k_gemm_tc<HID><<<gemmB, 256>>>(nullptr, W2, b2, a2);   // X = g_h1
    k_ex<<<edgeB, 256>>>(src, dst, ab2);
    k_agg<<<aggB, 256>>>(out);
}